// round 17
// baseline (speedup 1.0000x reference)
#include <cuda_runtime.h>
#include <cuda_bf16.h>
#include <cstdint>

// Problem constants
#define B_DIM   2048
#define P_DIM   50
#define K_DIM   28672            // 512*7*8
#define NP      56               // P padded to 56 (7 n8-tiles)
#define KS      37               // K splits -> grid 8*37=296 = exactly 2 CTAs/SM
#define KB      32               // K floats per pipeline stage
#define MT      256              // M tile (2x: each warp owns 32 rows)
#define MTILES  (B_DIM / MT)     // 8
#define STAGES  2
#define BPITCH  40               // bf16 pitch (80B rows; LDS.32 frag reads conflict-free)

// Uneven K split: 896 k-blocks = 8*25 + 29*24
#define KCNT(ks)   ((ks) < 8 ? 25 : 24)
#define KSTART(ks) (24 * (ks) + ((ks) < 8 ? (ks) : 8))

// Staged tiles: fp32, exact 128B rows, XOR granule swizzle
#define AS_BYTES (MT * KB * 4)               // 32768
#define BS_BYTES (NP * KB * 4)               // 7168
#define STAGE_BYTES (AS_BYTES + BS_BYTES)    // 39936
#define BF_BYTES (NP * BPITCH * 2)           // 4480 single shared bf16 B tile
#define SMEM_BYTES (STAGES * STAGE_BYTES + BF_BYTES)   // 84352 (2 CTAs/SM: 168KB < 228KB)

// ---------------------------------------------------------------------------
__device__ __forceinline__ void cpa16(uint32_t saddr, const void* gaddr) {
    asm volatile("cp.async.cg.shared.global [%0], [%1], 16;\n"
                 :: "r"(saddr), "l"(gaddr));
}
__device__ __forceinline__ void cpa16z(uint32_t saddr, const void* gaddr, int srcsz) {
    asm volatile("cp.async.cg.shared.global [%0], [%1], 16, %2;\n"
                 :: "r"(saddr), "l"(gaddr), "r"(srcsz));
}
__device__ __forceinline__ void cpa_commit() {
    asm volatile("cp.async.commit_group;\n" ::: "memory");
}
__device__ __forceinline__ void cpa_wait1() {
    asm volatile("cp.async.wait_group 1;\n" ::: "memory");
}
__device__ __forceinline__ uint32_t pack_bf16x2(float2 v) {
    __nv_bfloat162 h = __floats2bfloat162_rn(v.x, v.y);
    return *(uint32_t*)&h;
}
// vector reduction: out[0] += v0, out[1] += v1 in ONE LTS op (sm_90+)
__device__ __forceinline__ void red_v2(float* gaddr, float v0, float v1) {
    asm volatile("red.global.add.v2.f32 [%0], {%1, %2};\n"
                 :: "l"(gaddr), "f"(v0), "f"(v1) : "memory");
}

// ---------------------------------------------------------------------------
// Fused GEMM + distance accumulation, single kernel, MT=256:
// each warp owns 32 M-rows (two m16 tiles) -> B fragments amortized 2x.
// 2-stage cp.async fp32 pipeline; B converted fp32->bf16 into one shared
// tile per iter (warps 0-6; exact p2 from fp32 regs); x^2 fused in A frags.
// Block epilogue: v2-RED  x2_b + p2_p - 2*xp  into out[b,p] (relu unneeded).
// grid (MTILES, KS) = (8, 37) = 296 blocks, 256 threads = 8 warps.
// ---------------------------------------------------------------------------
__global__ void __launch_bounds__(256, 2) gemm_kernel(
        const float* __restrict__ x, const float* __restrict__ proto,
        float* __restrict__ out) {
    extern __shared__ char smem[];
    __nv_bfloat16* bbf = (__nv_bfloat16*)(smem + STAGES * STAGE_BYTES);

    const int mt    = blockIdx.x;
    const int ks    = blockIdx.y;
    const int NITER = KCNT(ks);
    const int t     = threadIdx.x;
    const int warp  = t >> 5;
    const int lane  = t & 31;
    const int q     = lane & 3;
    const int rr    = lane >> 2;      // 0..7
    const int b0    = mt * MT;
    const int k0    = KSTART(ks) * 32;

    // --- A cp.async mapping: 8 passes of 32 rows ---
    const int xrr = t >> 3;           // 0..31
    const int xch = t & 7;            // granule 0..7 (row = 8 granules = 128B)
    const float* xg0 = x + (size_t)(b0 + xrr) * K_DIM + k0 + xch * 4;
    const uint32_t a_sw = (uint32_t)(xch ^ ((xrr & 3) << 1));

    // --- B cp.async mapping (rows >= P_DIM zero-filled) ---
    const int prr = t >> 2;           // 0..63 (only < NP participate)
    const int pch = t & 3;
    const float* pg0 = proto + (size_t)prr * K_DIM + k0 + pch * 4;
    const uint32_t b_sw0 = (uint32_t)( pch      ^ ((prr & 3) << 1));
    const uint32_t b_sw1 = (uint32_t)((pch + 4) ^ ((prr & 3) << 1));
    const int psz = (prr < P_DIM) ? 16 : 0;

    const uint32_t smem_u = (uint32_t)__cvta_generic_to_shared(smem);

    auto issue = [&](int stage, int chunk) {
        const uint32_t sb = smem_u + (uint32_t)(stage * STAGE_BYTES);
        const float* xg = xg0 + chunk * KB;
        #pragma unroll
        for (int pass = 0; pass < 8; pass++) {
            cpa16(sb + (uint32_t)((xrr + pass * 32) * 128) + (a_sw << 4),
                  xg + (size_t)(pass * 32) * K_DIM);
        }
        if (prr < NP) {
            const float* pg = pg0 + chunk * KB;
            const uint32_t bb = sb + AS_BYTES + (uint32_t)(prr * 128);
            cpa16z(bb + (b_sw0 << 4), pg,      psz);
            cpa16z(bb + (b_sw1 << 4), pg + 16, psz);
        }
        cpa_commit();
    };

    // prologue: chunk 0 into stage 0
    issue(0, 0);

    // fragment rows: warp owns rows [warp*32, warp*32+32)
    const int r0 = warp * 32 + rr;    // + {0, 8, 16, 24}
    const uint32_t swf = (uint32_t)((rr & 3) << 1);  // rows differ by multiples of 8
    const int qg = q >> 1;
    const int qp = (q & 1) << 3;

    // convert-pass mapping (warps 0-6 = 224 threads)
    const int crow = t >> 2;
    const int cp0  = (t & 3) * 2;
    const uint32_t csw = (uint32_t)((crow & 3) << 1);

    float acc0[7][4], acc1[7][4];     // two m16 tiles per warp
    #pragma unroll
    for (int j = 0; j < 7; j++)
        #pragma unroll
        for (int c = 0; c < 4; c++) { acc0[j][c] = 0.f; acc1[j][c] = 0.f; }
    float x2a = 0.f, x2b = 0.f, x2c = 0.f, x2d = 0.f;
    float p2acc = 0.f;

    int stage = 0;
    for (int it = 0; it < NITER; ++it) {
        __syncthreads();                 // all warps done with stage^1 -> free
        if (it + 1 < NITER) issue(stage ^ 1, it + 1);
        else                cpa_commit();  // keep group counting uniform
        cpa_wait1();                     // chunk `it` complete (my copies)
        __syncthreads();                 // ALL threads' copies visible

        const char* sb = smem + stage * STAGE_BYTES;

        // --- B convert: fp32 stage -> shared bf16 tile; exact p2 for free ---
        if (t < 224) {
            const char* bsrc = sb + AS_BYTES + crow * 128;
            float4 v0 = *(const float4*)(bsrc + (cp0 << 4));
            float4 v1 = *(const float4*)(bsrc + ((cp0 + 1) << 4));
            p2acc += v0.x * v0.x + v0.y * v0.y + v0.z * v0.z + v0.w * v0.w
                   + v1.x * v1.x + v1.y * v1.y + v1.z * v1.z + v1.w * v1.w;
            const uint32_t g0 = (uint32_t)cp0 ^ csw;
            uint4 w;
            w.x = pack_bf16x2(make_float2(v0.x, v0.y));
            w.y = pack_bf16x2(make_float2(v0.z, v0.w));
            w.z = pack_bf16x2(make_float2(v1.x, v1.y));
            w.w = pack_bf16x2(make_float2(v1.z, v1.w));
            *(uint4*)((char*)bbf + crow * 80 + (g0 << 3)) = w;
        }
        __syncthreads();                 // bf16 tile ready

        stage ^= 1;

        #pragma unroll
        for (int kk = 0; kk < 2; ++kk) {
            const uint32_t g0 = (uint32_t)(kk * 4 + qg);
            const uint32_t o_lo = ((g0 ^ swf) << 4) + qp;
            const uint32_t o_hi = (((g0 + 2) ^ swf) << 4) + qp;
            // tile 0: rows r0, r0+8
            float2 a00 = *(const float2*)(sb + (r0     ) * 128 + o_lo);
            float2 a01 = *(const float2*)(sb + (r0     ) * 128 + o_hi);
            float2 a10 = *(const float2*)(sb + (r0 +  8) * 128 + o_lo);
            float2 a11 = *(const float2*)(sb + (r0 +  8) * 128 + o_hi);
            // tile 1: rows r0+16, r0+24
            float2 a20 = *(const float2*)(sb + (r0 + 16) * 128 + o_lo);
            float2 a21 = *(const float2*)(sb + (r0 + 16) * 128 + o_hi);
            float2 a30 = *(const float2*)(sb + (r0 + 24) * 128 + o_lo);
            float2 a31 = *(const float2*)(sb + (r0 + 24) * 128 + o_hi);
            x2a += a00.x * a00.x + a00.y * a00.y + a01.x * a01.x + a01.y * a01.y;
            x2b += a10.x * a10.x + a10.y * a10.y + a11.x * a11.x + a11.y * a11.y;
            x2c += a20.x * a20.x + a20.y * a20.y + a21.x * a21.x + a21.y * a21.y;
            x2d += a30.x * a30.x + a30.y * a30.y + a31.x * a31.x + a31.y * a31.y;
            uint32_t A00 = pack_bf16x2(a00), A01 = pack_bf16x2(a10);
            uint32_t A02 = pack_bf16x2(a01), A03 = pack_bf16x2(a11);
            uint32_t A10 = pack_bf16x2(a20), A11 = pack_bf16x2(a30);
            uint32_t A12 = pack_bf16x2(a21), A13 = pack_bf16x2(a31);
            const int kb = kk * 16 + q * 2;
            #pragma unroll
            for (int j = 0; j < 7; j++) {
                const int n = j * 8 + rr;
                uint32_t B0 = *(const uint32_t*)&bbf[n * BPITCH + kb];
                uint32_t B1 = *(const uint32_t*)&bbf[n * BPITCH + kb + 8];
                asm volatile(
                    "mma.sync.aligned.m16n8k16.row.col.f32.bf16.bf16.f32 "
                    "{%0,%1,%2,%3}, {%4,%5,%6,%7}, {%8,%9}, {%0,%1,%2,%3};\n"
                    : "+f"(acc0[j][0]), "+f"(acc0[j][1]), "+f"(acc0[j][2]), "+f"(acc0[j][3])
                    : "r"(A00), "r"(A01), "r"(A02), "r"(A03), "r"(B0), "r"(B1));
                asm volatile(
                    "mma.sync.aligned.m16n8k16.row.col.f32.bf16.bf16.f32 "
                    "{%0,%1,%2,%3}, {%4,%5,%6,%7}, {%8,%9}, {%0,%1,%2,%3};\n"
                    : "+f"(acc1[j][0]), "+f"(acc1[j][1]), "+f"(acc1[j][2]), "+f"(acc1[j][3])
                    : "r"(A10), "r"(A11), "r"(A12), "r"(A13), "r"(B0), "r"(B1));
            }
        }
    }

    // --- block epilogue ---

    // x^2 per row (quad reduce; all 4 lanes end with the row sum)
    x2a += __shfl_xor_sync(0xffffffffu, x2a, 1);
    x2a += __shfl_xor_sync(0xffffffffu, x2a, 2);
    x2b += __shfl_xor_sync(0xffffffffu, x2b, 1);
    x2b += __shfl_xor_sync(0xffffffffu, x2b, 2);
    x2c += __shfl_xor_sync(0xffffffffu, x2c, 1);
    x2c += __shfl_xor_sync(0xffffffffu, x2c, 2);
    x2d += __shfl_xor_sync(0xffffffffu, x2d, 1);
    x2d += __shfl_xor_sync(0xffffffffu, x2d, 2);

    // p^2 table from convert-thread partials (thread quad = one B row)
    __syncthreads();                      // done with pipeline smem
    float* p2s = (float*)smem;            // 56 floats
    if (t < 224) {
        float s = p2acc;
        s += __shfl_xor_sync(0xffffffffu, s, 1);
        s += __shfl_xor_sync(0xffffffffu, s, 2);
        if ((t & 3) == 0) p2s[t >> 2] = s;
    }
    __syncthreads();

    // v2 RED: out[b, n..n+1] += x2_row + p2_col - 2*xp  (relu unnecessary)
    float* outr0 = out + (size_t)(b0 + r0     ) * P_DIM;
    float* outr1 = out + (size_t)(b0 + r0 +  8) * P_DIM;
    float* outr2 = out + (size_t)(b0 + r0 + 16) * P_DIM;
    float* outr3 = out + (size_t)(b0 + r0 + 24) * P_DIM;
    const int ccol = q * 2;
    #pragma unroll
    for (int j = 0; j < 7; j++) {
        const int n0 = j * 8 + ccol;      // even; pair (n0, n0+1), 8B aligned
        if (n0 < P_DIM) {
            const float pv0 = p2s[n0];
            const float pv1 = p2s[n0 + 1];
            red_v2(outr0 + n0, x2a + pv0 - 2.f * acc0[j][0],
                               x2a + pv1 - 2.f * acc0[j][1]);
            red_v2(outr1 + n0, x2b + pv0 - 2.f * acc0[j][2],
                               x2b + pv1 - 2.f * acc0[j][3]);
            red_v2(outr2 + n0, x2c + pv0 - 2.f * acc1[j][0],
                               x2c + pv1 - 2.f * acc1[j][1]);
            red_v2(outr3 + n0, x2d + pv0 - 2.f * acc1[j][2],
                               x2d + pv1 - 2.f * acc1[j][3]);
        }
    }
}

// ---------------------------------------------------------------------------
extern "C" void kernel_launch(void* const* d_in, const int* in_sizes, int n_in,
                              void* d_out, int out_size) {
    const float* x     = (const float*)d_in[0];
    const float* proto = (const float*)d_in[1];
    if (in_sizes[0] == P_DIM * K_DIM) {  // defensive: swap if order differs
        x     = (const float*)d_in[1];
        proto = (const float*)d_in[0];
    }
    float* out = (float*)d_out;

    cudaFuncSetAttribute(gemm_kernel,
                         cudaFuncAttributeMaxDynamicSharedMemorySize, SMEM_BYTES);

    cudaMemsetAsync(out, 0, (size_t)B_DIM * P_DIM * sizeof(float));
    gemm_kernel<<<dim3(MTILES, KS), 256, SMEM_BYTES>>>(x, proto, out);
}